// round 5
// baseline (speedup 1.0000x reference)
#include <cuda_runtime.h>

// FiniteDifference: x [B=4, T=16, H=128, W=128, C=16] fp32
// out = concat(dy (d/dH), dx (d/dW), dz (d/dT)); central diff, zero pad.
//
// R5: axis-specialized CTAs. blockIdx.y in {0,1,2} selects which output
// (dy/dx/dz) a CTA produces, so each warp emits ONE linear write stream
// (better DRAM row locality) and needs only 2 loads (both L2 hits).
// Total DRAM traffic unchanged (201 MB writes); tests whether the
// ~5.3 TB/s write throughput is stream-mix-limited.

#define N4_TOTAL (4 * 16 * 128 * 128 * 4)  // 4,194,304 float4 elems per output

__device__ __forceinline__ float4 sub4(float4 a, float4 b) {
    return make_float4(a.x - b.x, a.y - b.y, a.z - b.z, a.w - b.w);
}

__global__ void __launch_bounds__(256)
fd_kernel(const float4* __restrict__ x, float4* __restrict__ out)
{
    int i = blockIdx.x * blockDim.x + threadIdx.x;
    int axis = blockIdx.y;  // 0: dy (H), 1: dx (W), 2: dz (T)

    const float4 zero = make_float4(0.f, 0.f, 0.f, 0.f);
    float4 p, m;

    if (axis == 0) {
        int h = (i >> 9) & 127;
        p = (h < 127) ? x[i + 512] : zero;
        m = (h > 0)   ? x[i - 512] : zero;
        __stcs(&out[i], sub4(p, m));
    } else if (axis == 1) {
        int w = (i >> 2) & 127;
        p = (w < 127) ? x[i + 4] : zero;
        m = (w > 0)   ? x[i - 4] : zero;
        __stcs(&out[i + N4_TOTAL], sub4(p, m));
    } else {
        int t = (i >> 16) & 15;
        p = (t < 15) ? x[i + 65536] : zero;
        m = (t > 0)  ? x[i - 65536] : zero;
        __stcs(&out[i + 2 * N4_TOTAL], sub4(p, m));
    }
}

extern "C" void kernel_launch(void* const* d_in, const int* in_sizes, int n_in,
                              void* d_out, int out_size)
{
    const float4* x = (const float4*)d_in[0];
    float4* out = (float4*)d_out;

    dim3 grid(N4_TOTAL / 256, 3, 1);
    fd_kernel<<<grid, 256>>>(x, out);
}

// round 6
// speedup vs baseline: 1.5169x; 1.5169x over previous
#include <cuda_runtime.h>
#include <cstdint>

// FiniteDifference: x [B=4, T=16, H=128, W=128, C=16] fp32
// out = concat(dy (d/dH), dx (d/dW), dz (d/dT)); central diff, zero pad.
//
// R6: R1's fused compute (traffic-optimal: ~201 MB compulsory writes, reads
// L2-resident) + TMA bulk stores. Each 256-thread CTA computes 3 x 4 KB
// output tiles into SMEM, then issues 3 cp.async.bulk (shared->global)
// stores. Bulk writes give DRAM long sequential bursts per stream instead
// of thousands of interleaved 512 B warp-store fronts.

#define N4_TOTAL (4 * 16 * 128 * 128 * 4)  // 4,194,304 float4 elems per output

__device__ __forceinline__ float4 sub4(float4 a, float4 b) {
    return make_float4(a.x - b.x, a.y - b.y, a.z - b.z, a.w - b.w);
}

__device__ __forceinline__ uint32_t smem_u32(const void* p) {
    uint32_t a;
    asm("{ .reg .u64 t; cvta.to.shared.u64 t, %1; cvt.u32.u64 %0, t; }"
        : "=r"(a) : "l"(p));
    return a;
}

__global__ void __launch_bounds__(256)
fd_kernel(const float4* __restrict__ x, float4* __restrict__ out)
{
    __shared__ float4 stage[3][256];   // 12 KB

    int tid = threadIdx.x;
    int i = blockIdx.x * 256 + tid;

    int w = (i >> 2)  & 127;
    int h = (i >> 9)  & 127;
    int t = (i >> 16) & 15;

    const float4 zero = make_float4(0.f, 0.f, 0.f, 0.f);

    float4 hp = (h < 127) ? x[i + 512]   : zero;
    float4 hm = (h > 0)   ? x[i - 512]   : zero;
    float4 wp = (w < 127) ? x[i + 4]     : zero;
    float4 wm = (w > 0)   ? x[i - 4]     : zero;
    float4 tp = (t < 15)  ? x[i + 65536] : zero;
    float4 tm = (t > 0)   ? x[i - 65536] : zero;

    stage[0][tid] = sub4(hp, hm);   // dy
    stage[1][tid] = sub4(wp, wm);   // dx
    stage[2][tid] = sub4(tp, tm);   // dz

    __syncthreads();
    // Order generic-proxy SMEM writes before async-proxy (TMA) reads.
    asm volatile("fence.proxy.async.shared::cta;" ::: "memory");

    if (tid == 0) {
        long long base = (long long)blockIdx.x * 256;
        float4* dst0 = out + base;
        float4* dst1 = out + base + N4_TOTAL;
        float4* dst2 = out + base + 2LL * N4_TOTAL;
        uint32_t s0 = smem_u32(&stage[0][0]);
        uint32_t s1 = smem_u32(&stage[1][0]);
        uint32_t s2 = smem_u32(&stage[2][0]);
        asm volatile("cp.async.bulk.global.shared::cta.bulk_group [%0], [%1], %2;"
                     :: "l"(dst0), "r"(s0), "n"(4096) : "memory");
        asm volatile("cp.async.bulk.global.shared::cta.bulk_group [%0], [%1], %2;"
                     :: "l"(dst1), "r"(s1), "n"(4096) : "memory");
        asm volatile("cp.async.bulk.global.shared::cta.bulk_group [%0], [%1], %2;"
                     :: "l"(dst2), "r"(s2), "n"(4096) : "memory");
        asm volatile("cp.async.bulk.commit_group;" ::: "memory");
        // Wait until TMA has finished READING smem before CTA may exit.
        asm volatile("cp.async.bulk.wait_group.read 0;" ::: "memory");
    }
    __syncthreads();
}

extern "C" void kernel_launch(void* const* d_in, const int* in_sizes, int n_in,
                              void* d_out, int out_size)
{
    const float4* x = (const float4*)d_in[0];
    float4* out = (float4*)d_out;

    fd_kernel<<<N4_TOTAL / 256, 256>>>(x, out);
}